// round 2
// baseline (speedup 1.0000x reference)
#include <cuda_runtime.h>
#include <math.h>

#define Bb 64
#define Pp 8
#define Nn 4096
#define Dd 256
#define Mm 4096
#define BP 512
#define TEMPC 0.1f
#define EPSC 1e-8f

// ---- static device scratch (no allocations allowed) ----
__device__ float    g_sim[(size_t)Bb * Nn * Pp];  // [b][n][p]; raw sim, then exp()
__device__ float    g_rnorm[Bb * Nn];
__device__ float    g_pn[BP * Dd];                // normalized prototypes
__device__ unsigned g_max[BP];                    // ordered-uint float max
__device__ float    g_invZ[BP];
__device__ float    g_tau[BP];
__device__ int      g_cnt[BP];
__device__ int      g_idx[Bb * Nn];
__device__ float    g_wsel[Bb * Nn];
__device__ float    g_msum[Bb * 16 * Pp];
__device__ float    g_orgn[Mm];

__device__ __forceinline__ unsigned f2ord(float f) {
    unsigned u = __float_as_uint(f);
    return (u & 0x80000000u) ? ~u : (u | 0x80000000u);
}
__device__ __forceinline__ float ord2f(unsigned u) {
    return (u & 0x80000000u) ? __uint_as_float(u & 0x7FFFFFFFu) : __uint_as_float(~u);
}

// full warp reduce of 8 per-lane values; afterwards every lane holds totals
template<bool MX>
__device__ __forceinline__ void red8(float v[8]) {
#pragma unroll
    for (int off = 16; off; off >>= 1) {
#pragma unroll
        for (int p = 0; p < 8; p++) {
            float o = __shfl_xor_sync(0xFFFFFFFFu, v[p], off);
            v[p] = MX ? fmaxf(v[p], o) : (v[p] + o);
        }
    }
}

__device__ __forceinline__ float block_sum256(float v, float* r8) {
#pragma unroll
    for (int off = 16; off; off >>= 1) v += __shfl_xor_sync(0xFFFFFFFFu, v, off);
    if ((threadIdx.x & 31) == 0) r8[threadIdx.x >> 5] = v;
    __syncthreads();
    if (threadIdx.x == 0) {
        float t = 0.f;
#pragma unroll
        for (int w = 0; w < 8; w++) t += r8[w];
        r8[0] = t;
    }
    __syncthreads();
    return r8[0];
}

// ---- normalize input prototypes; init tau/max ----
__global__ void __launch_bounds__(256) k_norm0(const float* __restrict__ pin) {
    __shared__ float r8[8];
    int bp = blockIdx.x, tid = threadIdx.x;
    float v = pin[(size_t)bp * Dd + tid];
    float ss = block_sum256(v * v, r8);
    g_pn[(size_t)bp * Dd + tid] = v / fmaxf(sqrtf(ss), EPSC);
    if (tid == 0) { g_tau[bp] = 0.1f; g_max[bp] = 0u; }
}

// ---- per-row rnorm of feats_org ----
__global__ void __launch_bounds__(256) k_orgnorm(const float* __restrict__ forg) {
    __shared__ float r8[8];
    int m = blockIdx.x, tid = threadIdx.x;
    float v = forg[(size_t)m * Dd + tid];
    float ss = block_sum256(v * v, r8);
    if (tid == 0) g_orgn[m] = 1.f / fmaxf(sqrtf(ss), EPSC);
}

// ---- sim[b,n,p] = pn[b,p] . fn[b,n]; per-(b,p) max; optional density partials ----
template<bool FIRST, bool DENS>
__global__ void __launch_bounds__(256) k_sim(const float* __restrict__ feats) {
    int b = blockIdx.x >> 4, chunk = blockIdx.x & 15;
    int tid = threadIdx.x, lane = tid & 31, wid = tid >> 5;
    __shared__ float4 pn_s[Pp * 64];   // 8 KB
    __shared__ float  fs[256 * 20];    // 20 KB padded tile
    __shared__ float  red[8 * 8];

    const float4* psrc = (const float4*)g_pn + (size_t)b * (Pp * 64);
    for (int i = tid; i < Pp * 64; i += 256) pn_s[i] = psrc[i];
    const float4* fbase = (const float4*)feats + ((size_t)b * Nn + chunk * 256) * 64;

    float acc[8];
#pragma unroll
    for (int p = 0; p < 8; p++) acc[p] = 0.f;
    float sq = 0.f;

    for (int s = 0; s < 16; s++) {
        __syncthreads();
#pragma unroll
        for (int k = 0; k < 4; k++) {
            int idx = k * 256 + tid;
            int row = idx >> 2, j = idx & 3;
            *(float4*)&fs[row * 20 + j * 4] = fbase[(size_t)row * 64 + s * 4 + j];
        }
        __syncthreads();
#pragma unroll
        for (int j = 0; j < 4; j++) {
            float4 f = *(const float4*)&fs[tid * 20 + j * 4];
            if (FIRST) {
                sq = fmaf(f.x, f.x, sq); sq = fmaf(f.y, f.y, sq);
                sq = fmaf(f.z, f.z, sq); sq = fmaf(f.w, f.w, sq);
            }
#pragma unroll
            for (int p = 0; p < 8; p++) {
                float4 q = pn_s[p * 64 + s * 4 + j];
                acc[p] = fmaf(f.x, q.x, acc[p]); acc[p] = fmaf(f.y, q.y, acc[p]);
                acc[p] = fmaf(f.z, q.z, acc[p]); acc[p] = fmaf(f.w, q.w, acc[p]);
            }
        }
    }

    int n = chunk * 256 + tid;
    float rn;
    if (FIRST) { rn = 1.f / fmaxf(sqrtf(sq), EPSC); g_rnorm[b * Nn + n] = rn; }
    else rn = g_rnorm[b * Nn + n];

    float sim[8];
#pragma unroll
    for (int p = 0; p < 8; p++) sim[p] = acc[p] * rn;
    float4* o = (float4*)(g_sim + ((size_t)b * Nn + n) * 8);
    o[0] = make_float4(sim[0], sim[1], sim[2], sim[3]);
    o[1] = make_float4(sim[4], sim[5], sim[6], sim[7]);

    // per-(b,p) exact max via ordered-uint atomics
    float mv[8];
#pragma unroll
    for (int p = 0; p < 8; p++) mv[p] = sim[p];
    red8<true>(mv);
    if (lane < 8) red[wid * 8 + lane] = mv[lane];
    __syncthreads();
    if (tid < 8) {
        float m = red[tid];
#pragma unroll
        for (int w = 1; w < 8; w++) m = fmaxf(m, red[w * 8 + tid]);
        atomicMax(&g_max[b * 8 + tid], f2ord(m));
    }

    if (DENS) {   // this sim == reference's sim2 of the previous iteration
        int a = g_idx[b * Nn + n];
        float dv[8];
#pragma unroll
        for (int p = 0; p < 8; p++) dv[p] = (p == a) ? sim[p] : 0.f;
        red8<false>(dv);
        __syncthreads();
        if (lane < 8) red[wid * 8 + lane] = dv[lane];
        __syncthreads();
        if (tid < 8) {
            float s2 = red[tid];
#pragma unroll
            for (int w = 1; w < 8; w++) s2 += red[w * 8 + tid];
            g_msum[((size_t)b * 16 + chunk) * 8 + tid] = s2;
        }
    }
}

// ---- tau from density partials + counts (must run BEFORE k_stats resets cnt) ----
__global__ void k_tau() {
    int bp = threadIdx.x;           // 512 threads
    int b = bp >> 3, p = bp & 7;
    float s = 0.f;
#pragma unroll
    for (int c = 0; c < 16; c++) s += g_msum[((size_t)b * 16 + c) * 8 + p];
    int cnt = g_cnt[bp];
    float mean = s / (float)(cnt >= 1 ? cnt : 1);
    float dens = 1.f - (cnt >= 1 ? mean : 0.f);
    g_tau[bp] = fmaxf(dens, 1e-10f);
}

// ---- exp((sim-max)/(T*tau)) in place; Z per (b,p); reset cnt ----
__global__ void __launch_bounds__(512) k_stats() {
    int b = blockIdx.x, tid = threadIdx.x, lane = tid & 31, wid = tid >> 5;
    __shared__ float mx[8], is[8], red[16 * 8];
    if (tid < 8) {
        mx[tid] = ord2f(g_max[b * 8 + tid]);
        is[tid] = 1.f / (TEMPC * g_tau[b * 8 + tid]);
        g_cnt[b * 8 + tid] = 0;
    }
    __syncthreads();
    float z[8];
#pragma unroll
    for (int p = 0; p < 8; p++) z[p] = 0.f;
    for (int k = 0; k < 8; k++) {
        float4* p4 = (float4*)(g_sim + ((size_t)b * Nn + k * 512 + tid) * 8);
        float4 a = p4[0], c = p4[1];
        a.x = expf((a.x - mx[0]) * is[0]); z[0] += a.x;
        a.y = expf((a.y - mx[1]) * is[1]); z[1] += a.y;
        a.z = expf((a.z - mx[2]) * is[2]); z[2] += a.z;
        a.w = expf((a.w - mx[3]) * is[3]); z[3] += a.w;
        c.x = expf((c.x - mx[4]) * is[4]); z[4] += c.x;
        c.y = expf((c.y - mx[5]) * is[5]); z[5] += c.y;
        c.z = expf((c.z - mx[6]) * is[6]); z[6] += c.z;
        c.w = expf((c.w - mx[7]) * is[7]); z[7] += c.w;
        p4[0] = a; p4[1] = c;
    }
    red8<false>(z);
    if (lane < 8) red[wid * 8 + lane] = z[lane];
    __syncthreads();
    if (tid < 8) {
        float s = red[tid];
#pragma unroll
        for (int w = 1; w < 16; w++) s += red[w * 8 + tid];
        g_invZ[b * 8 + tid] = 1.f / s;
    }
}

// ---- weight = e*invZ; argmax over p (first max); counts via int atomics ----
__global__ void __launch_bounds__(256) k_assign() {
    int b = blockIdx.x >> 4, chunk = blockIdx.x & 15;
    int tid = threadIdx.x, lane = tid & 31;
    int n = chunk * 256 + tid;
    __shared__ float iz[8];
    if (tid < 8) iz[tid] = g_invZ[b * 8 + tid];
    __syncthreads();
    const float4* p4 = (const float4*)(g_sim + ((size_t)b * Nn + n) * 8);
    float4 a = p4[0], c = p4[1];
    float w[8] = { a.x * iz[0], a.y * iz[1], a.z * iz[2], a.w * iz[3],
                   c.x * iz[4], c.y * iz[5], c.z * iz[6], c.w * iz[7] };
    int bi = 0; float bw = w[0];
#pragma unroll
    for (int p = 1; p < 8; p++) if (w[p] > bw) { bw = w[p]; bi = p; }
    g_idx[b * Nn + n] = bi;
    g_wsel[b * Nn + n] = bw;
    int myc = 0;
#pragma unroll
    for (int p = 0; p < 8; p++) {
        unsigned mk = __ballot_sync(0xFFFFFFFFu, bi == p);
        if (lane == p) myc = __popc(mk);
    }
    if (lane < 8) atomicAdd(&g_cnt[b * 8 + lane], myc);
}

// ---- prototypes[b,p] = sum_{n: idx==p} wsel[n]*feats[b,n]; fused normalize ----
__global__ void __launch_bounds__(256) k_update(const float* __restrict__ feats,
                                                float* __restrict__ outp) {
    int bp = blockIdx.x, b = bp >> 3, p = bp & 7;
    int tid = threadIdx.x, lane = tid & 31, wid = tid >> 5;
    __shared__ unsigned short list[8][512];
    __shared__ float sacc[8][256];
    __shared__ float r8[8];

    const int* idxp = g_idx + b * Nn;
    int cntw = 0, base = wid * 512;
    for (int g = 0; g < 16; g++) {
        int n = base + g * 32 + lane;
        int a = idxp[n];
        unsigned mk = __ballot_sync(0xFFFFFFFFu, a == p);
        if (a == p)
            list[wid][cntw + __popc(mk & ((1u << lane) - 1u))] = (unsigned short)n;
        cntw += __popc(mk);
    }
    __syncwarp();

    float4 a0 = make_float4(0, 0, 0, 0), a1 = make_float4(0, 0, 0, 0);
    const float* fb = feats + (size_t)b * Nn * Dd;
    const float* wp = g_wsel + b * Nn;
    int i = 0;
    for (; i + 1 < cntw; i += 2) {
        int n1 = list[wid][i], n2 = list[wid][i + 1];
        float w1 = wp[n1], w2 = wp[n2];
        float4 f0 = *(const float4*)(fb + (size_t)n1 * Dd + (lane << 2));
        float4 f1 = *(const float4*)(fb + (size_t)n1 * Dd + 128 + (lane << 2));
        float4 h0 = *(const float4*)(fb + (size_t)n2 * Dd + (lane << 2));
        float4 h1 = *(const float4*)(fb + (size_t)n2 * Dd + 128 + (lane << 2));
        a0.x = fmaf(w1, f0.x, a0.x); a0.y = fmaf(w1, f0.y, a0.y);
        a0.z = fmaf(w1, f0.z, a0.z); a0.w = fmaf(w1, f0.w, a0.w);
        a1.x = fmaf(w1, f1.x, a1.x); a1.y = fmaf(w1, f1.y, a1.y);
        a1.z = fmaf(w1, f1.z, a1.z); a1.w = fmaf(w1, f1.w, a1.w);
        a0.x = fmaf(w2, h0.x, a0.x); a0.y = fmaf(w2, h0.y, a0.y);
        a0.z = fmaf(w2, h0.z, a0.z); a0.w = fmaf(w2, h0.w, a0.w);
        a1.x = fmaf(w2, h1.x, a1.x); a1.y = fmaf(w2, h1.y, a1.y);
        a1.z = fmaf(w2, h1.z, a1.z); a1.w = fmaf(w2, h1.w, a1.w);
    }
    if (i < cntw) {
        int n1 = list[wid][i];
        float w1 = wp[n1];
        float4 f0 = *(const float4*)(fb + (size_t)n1 * Dd + (lane << 2));
        float4 f1 = *(const float4*)(fb + (size_t)n1 * Dd + 128 + (lane << 2));
        a0.x = fmaf(w1, f0.x, a0.x); a0.y = fmaf(w1, f0.y, a0.y);
        a0.z = fmaf(w1, f0.z, a0.z); a0.w = fmaf(w1, f0.w, a0.w);
        a1.x = fmaf(w1, f1.x, a1.x); a1.y = fmaf(w1, f1.y, a1.y);
        a1.z = fmaf(w1, f1.z, a1.z); a1.w = fmaf(w1, f1.w, a1.w);
    }
    *(float4*)&sacc[wid][lane << 2] = a0;
    *(float4*)&sacc[wid][128 + (lane << 2)] = a1;
    __syncthreads();

    float v = 0.f;
#pragma unroll
    for (int w = 0; w < 8; w++) v += sacc[w][tid];
    float ss = block_sum256(v * v, r8);
    float rn = 1.f / fmaxf(sqrtf(ss), EPSC);
    outp[(size_t)bp * Dd + tid] = v;            // raw prototype (output part 1)
    g_pn[(size_t)bp * Dd + tid] = v * rn;       // normalized for next pass
    if (tid == 0) g_max[bp] = 0u;               // reset for next sim pass
}

// ---- final sim_map[b,p,m] = pn . l2norm(feats_org) ----
__global__ void __launch_bounds__(256) k_simmap(const float* __restrict__ forg,
                                                float* __restrict__ out) {
    int b = blockIdx.x >> 4, chunk = blockIdx.x & 15;
    int tid = threadIdx.x;
    __shared__ float4 pn_s[Pp * 64];
    __shared__ float  fs[256 * 20];

    const float4* psrc = (const float4*)g_pn + (size_t)b * (Pp * 64);
    for (int i = tid; i < Pp * 64; i += 256) pn_s[i] = psrc[i];
    const float4* fbase = (const float4*)forg + (size_t)chunk * 256 * 64;

    float acc[8];
#pragma unroll
    for (int p = 0; p < 8; p++) acc[p] = 0.f;

    for (int s = 0; s < 16; s++) {
        __syncthreads();
#pragma unroll
        for (int k = 0; k < 4; k++) {
            int idx = k * 256 + tid;
            int row = idx >> 2, j = idx & 3;
            *(float4*)&fs[row * 20 + j * 4] = fbase[(size_t)row * 64 + s * 4 + j];
        }
        __syncthreads();
#pragma unroll
        for (int j = 0; j < 4; j++) {
            float4 f = *(const float4*)&fs[tid * 20 + j * 4];
#pragma unroll
            for (int p = 0; p < 8; p++) {
                float4 q = pn_s[p * 64 + s * 4 + j];
                acc[p] = fmaf(f.x, q.x, acc[p]); acc[p] = fmaf(f.y, q.y, acc[p]);
                acc[p] = fmaf(f.z, q.z, acc[p]); acc[p] = fmaf(f.w, q.w, acc[p]);
            }
        }
    }
    int m = chunk * 256 + tid;
    float rn = g_orgn[m];
#pragma unroll
    for (int p = 0; p < 8; p++)
        out[((size_t)b * Pp + p) * Mm + m] = acc[p] * rn;
}

extern "C" void kernel_launch(void* const* d_in, const int* in_sizes, int n_in,
                              void* d_out, int out_size) {
    const float* protos = (const float*)d_in[0];
    const float* feats  = (const float*)d_in[1];
    const float* forg   = (const float*)d_in[2];
    float* out = (float*)d_out;

    k_norm0<<<BP, 256>>>(protos);
    k_orgnorm<<<Mm, 256>>>(forg);

    // iteration 1 (tau = 0.1 scalar)
    k_sim<true, false><<<Bb * 16, 256>>>(feats);
    k_stats<<<Bb, 512>>>();
    k_assign<<<Bb * 16, 256>>>();
    k_update<<<BP, 256>>>(feats, out);

    // iterations 2..5: sim pass doubles as previous iteration's density pass
    for (int it = 0; it < 4; it++) {
        k_sim<false, true><<<Bb * 16, 256>>>(feats);
        k_tau<<<1, 512>>>();
        k_stats<<<Bb, 512>>>();
        k_assign<<<Bb * 16, 256>>>();
        k_update<<<BP, 256>>>(feats, out);
    }

    k_simmap<<<Bb * 16, 256>>>(forg, out + (size_t)BP * Dd);
}

// round 3
// speedup vs baseline: 1.7221x; 1.7221x over previous
#include <cuda_runtime.h>
#include <math.h>

#define Bb 64
#define Pp 8
#define Nn 4096
#define Dd 256
#define Mm 4096
#define BPc 512
#define EPSC 1e-8f
#define FULLW 0xFFFFFFFFu

// ---- static device scratch ----
__device__ float    g_sim[(size_t)Bb * Nn * Pp];   // raw sim [b][n][p], 8MB
__device__ float    g_rnorm[Bb * Nn];
__device__ float    g_pn[BPc * Dd];                // normalized prototypes
__device__ unsigned g_max[BPc];                    // ordered-uint float max
__device__ float    g_isv[BPc];                    // 1/(0.1*tau)
__device__ float    g_zpart[Bb * 4 * Pp];          // Z partials (4 per bp)
__device__ int      g_cnt[2][BPc];                 // double-buffered counts
__device__ int      g_idx[Bb * Nn];
__device__ float    g_msum[Bb * 16 * Pp];          // density partials
__device__ float    g_ppart[(size_t)Bb * 8 * Pp * Dd];  // proto partials, 4MB

__device__ __forceinline__ unsigned f2ord(float f) {
    unsigned u = __float_as_uint(f);
    return (u & 0x80000000u) ? ~u : (u | 0x80000000u);
}
__device__ __forceinline__ float ord2f(unsigned u) {
    return (u & 0x80000000u) ? __uint_as_float(u & 0x7FFFFFFFu) : __uint_as_float(~u);
}

template<bool MX>
__device__ __forceinline__ void red8(float v[8]) {
#pragma unroll
    for (int off = 16; off; off >>= 1) {
#pragma unroll
        for (int p = 0; p < 8; p++) {
            float o = __shfl_xor_sync(FULLW, v[p], off);
            v[p] = MX ? fmaxf(v[p], o) : (v[p] + o);
        }
    }
}

__device__ __forceinline__ float block_sum256(float v, float* r8) {
#pragma unroll
    for (int off = 16; off; off >>= 1) v += __shfl_xor_sync(FULLW, v, off);
    if ((threadIdx.x & 31) == 0) r8[threadIdx.x >> 5] = v;
    __syncthreads();
    if (threadIdx.x == 0) {
        float t = 0.f;
#pragma unroll
        for (int w = 0; w < 8; w++) t += r8[w];
        r8[0] = t;
    }
    __syncthreads();
    return r8[0];
}

// ---- init: normalize prototypes, zero state ----
__global__ void __launch_bounds__(256) k_norm0(const float* __restrict__ pin) {
    __shared__ float r8[8];
    int bp = blockIdx.x, tid = threadIdx.x;
    float v = pin[(size_t)bp * Dd + tid];
    float ss = block_sum256(v * v, r8);
    g_pn[(size_t)bp * Dd + tid] = v / fmaxf(sqrtf(ss), EPSC);
    if (tid == 0) { g_max[bp] = 0u; g_cnt[0][bp] = 0; g_cnt[1][bp] = 0; }
}

// ---- sim pass: pipelined smem staging; per-(b,p) max; optional density ----
template<bool FIRST, bool DENS>
__global__ void __launch_bounds__(256) k_sim(const float* __restrict__ feats) {
    int b = blockIdx.x >> 4, c = blockIdx.x & 15;
    int tid = threadIdx.x, lane = tid & 31, wid = tid >> 5;
    __shared__ float4 pn_s[512];           // 8 KB
    __shared__ float  fs[2][256 * 20];     // 40 KB (exactly 48KB total)
    float* red = &fs[0][0];                // overlay after main loop

    const float4* psrc = (const float4*)g_pn + (size_t)b * 512;
    for (int i = tid; i < 512; i += 256) pn_s[i] = psrc[i];

    const float4* fbase = (const float4*)feats + ((size_t)b * Nn + c * 256) * 64;
    int rrow = tid >> 2, rj = tid & 3;
    const float4* gptr[4];
    int soff[4];
#pragma unroll
    for (int k = 0; k < 4; k++) {
        gptr[k] = fbase + (size_t)(k * 64 + rrow) * 64 + rj;
        soff[k] = (k * 64 + rrow) * 20 + rj * 4;
    }

    float4 r0[4];
#pragma unroll
    for (int k = 0; k < 4; k++) r0[k] = gptr[k][0];
#pragma unroll
    for (int k = 0; k < 4; k++) *(float4*)&fs[0][soff[k]] = r0[k];
    __syncthreads();

    float acc[8];
#pragma unroll
    for (int p = 0; p < 8; p++) acc[p] = 0.f;
    float sq = 0.f;

    for (int s = 0; s < 16; s++) {
        int buf = s & 1;
        if (s + 1 < 16) {
#pragma unroll
            for (int k = 0; k < 4; k++) r0[k] = gptr[k][(s + 1) * 4];
        }
#pragma unroll
        for (int j = 0; j < 4; j++) {
            float4 f = *(const float4*)&fs[buf][tid * 20 + j * 4];
            if (FIRST) {
                sq = fmaf(f.x, f.x, sq); sq = fmaf(f.y, f.y, sq);
                sq = fmaf(f.z, f.z, sq); sq = fmaf(f.w, f.w, sq);
            }
#pragma unroll
            for (int p = 0; p < 8; p++) {
                float4 q = pn_s[p * 64 + s * 4 + j];
                acc[p] = fmaf(f.x, q.x, acc[p]); acc[p] = fmaf(f.y, q.y, acc[p]);
                acc[p] = fmaf(f.z, q.z, acc[p]); acc[p] = fmaf(f.w, q.w, acc[p]);
            }
        }
        if (s + 1 < 16) {
#pragma unroll
            for (int k = 0; k < 4; k++) *(float4*)&fs[buf ^ 1][soff[k]] = r0[k];
        }
        __syncthreads();
    }

    int n = c * 256 + tid;
    float rn;
    if (FIRST) { rn = 1.f / fmaxf(sqrtf(sq), EPSC); g_rnorm[b * Nn + n] = rn; }
    else rn = g_rnorm[b * Nn + n];

    float sim[8];
#pragma unroll
    for (int p = 0; p < 8; p++) sim[p] = acc[p] * rn;
    float4* o = (float4*)(g_sim + ((size_t)b * Nn + n) * 8);
    o[0] = make_float4(sim[0], sim[1], sim[2], sim[3]);
    o[1] = make_float4(sim[4], sim[5], sim[6], sim[7]);

    float mv[8];
#pragma unroll
    for (int p = 0; p < 8; p++) mv[p] = sim[p];
    red8<true>(mv);
    if (lane < 8) red[wid * 8 + lane] = mv[lane];
    __syncthreads();
    if (tid < 8) {
        float m = red[tid];
#pragma unroll
        for (int w = 1; w < 8; w++) m = fmaxf(m, red[w * 8 + tid]);
        atomicMax(&g_max[b * 8 + tid], f2ord(m));
    }

    if (DENS) {   // this sim == reference's sim2 of the previous iteration
        int a = g_idx[b * Nn + n];
        float dv[8];
#pragma unroll
        for (int p = 0; p < 8; p++) dv[p] = (p == a) ? sim[p] : 0.f;
        red8<false>(dv);
        __syncthreads();
        if (lane < 8) red[wid * 8 + lane] = dv[lane];
        __syncthreads();
        if (tid < 8) {
            float s2 = red[tid];
#pragma unroll
            for (int w = 1; w < 8; w++) s2 += red[w * 8 + tid];
            g_msum[((size_t)b * 16 + c) * 8 + tid] = s2;
        }
    }
}

// ---- stats: tau + Z partials (grid 256 = b x 4 quarters) ----
template<bool HAS_TAU>
__global__ void __launch_bounds__(256) k_stats(int par) {
    int b = blockIdx.x >> 2, q = blockIdx.x & 3;
    int tid = threadIdx.x, lane = tid & 31, wid = tid >> 5;
    __shared__ float mxs[8], iss[8], red[64];
    if (tid < 8) {
        mxs[tid] = ord2f(g_max[b * 8 + tid]);
        float is;
        if (HAS_TAU) {
            float s = 0.f;
#pragma unroll
            for (int c = 0; c < 16; c++) s += g_msum[((size_t)b * 16 + c) * 8 + tid];
            int cnt = g_cnt[par][b * 8 + tid];
            float mean = s / (float)(cnt >= 1 ? cnt : 1);
            float dens = (cnt >= 1) ? (1.f - mean) : 1.f;
            is = 1.f / (0.1f * fmaxf(dens, 1e-10f));
        } else {
            is = 100.f;   // 1/(TEMP*tau0) = 1/(0.1*0.1)
        }
        iss[tid] = is;
        if (q == 0) g_isv[b * 8 + tid] = is;
    }
    __syncthreads();
    float z[8];
#pragma unroll
    for (int p = 0; p < 8; p++) z[p] = 0.f;
    for (int k = 0; k < 4; k++) {
        int n = q * 1024 + k * 256 + tid;
        const float4* p4 = (const float4*)(g_sim + ((size_t)b * Nn + n) * 8);
        float4 a = p4[0], c = p4[1];
        z[0] += expf((a.x - mxs[0]) * iss[0]);
        z[1] += expf((a.y - mxs[1]) * iss[1]);
        z[2] += expf((a.z - mxs[2]) * iss[2]);
        z[3] += expf((a.w - mxs[3]) * iss[3]);
        z[4] += expf((c.x - mxs[4]) * iss[4]);
        z[5] += expf((c.y - mxs[5]) * iss[5]);
        z[6] += expf((c.z - mxs[6]) * iss[6]);
        z[7] += expf((c.w - mxs[7]) * iss[7]);
    }
    red8<false>(z);
    if (lane < 8) red[wid * 8 + lane] = z[lane];
    __syncthreads();
    if (tid < 8) {
        float s = red[tid];
#pragma unroll
        for (int w = 1; w < 8; w++) s += red[w * 8 + tid];
        g_zpart[((size_t)b * 4 + q) * 8 + tid] = s;
    }
}

// ---- streaming update: fused assign + partial prototype accumulation ----
__global__ void __launch_bounds__(256, 2) k_update(const float* __restrict__ feats,
                                                   int parw) {
    int b = blockIdx.x >> 3, ch = blockIdx.x & 7;
    int tid = threadIdx.x, lane = tid & 31, wid = tid >> 5;
    __shared__ float mxs[8], iss[8], izs[8];
    __shared__ float buf[4][2048];   // 32 KB

    if (tid < 8) {
        mxs[tid] = ord2f(g_max[b * 8 + tid]);
        iss[tid] = g_isv[b * 8 + tid];
        float z = 0.f;
#pragma unroll
        for (int q = 0; q < 4; q++) z += g_zpart[((size_t)b * 4 + q) * 8 + tid];
        izs[tid] = 1.f / z;
    }
    __syncthreads();

    float acc[8][8];
#pragma unroll
    for (int p = 0; p < 8; p++)
#pragma unroll
        for (int j = 0; j < 8; j++) acc[p][j] = 0.f;
    int cc = 0;

#pragma unroll 1
    for (int g = 0; g < 2; g++) {
        int nb = ch * 512 + wid * 64 + g * 32;
        int n = nb + lane;
        const float4* sp = (const float4*)(g_sim + ((size_t)b * Nn + n) * 8);
        float4 s0 = sp[0], s1 = sp[1];
        float w[8];
        w[0] = expf((s0.x - mxs[0]) * iss[0]) * izs[0];
        w[1] = expf((s0.y - mxs[1]) * iss[1]) * izs[1];
        w[2] = expf((s0.z - mxs[2]) * iss[2]) * izs[2];
        w[3] = expf((s0.w - mxs[3]) * iss[3]) * izs[3];
        w[4] = expf((s1.x - mxs[4]) * iss[4]) * izs[4];
        w[5] = expf((s1.y - mxs[5]) * iss[5]) * izs[5];
        w[6] = expf((s1.z - mxs[6]) * iss[6]) * izs[6];
        w[7] = expf((s1.w - mxs[7]) * iss[7]) * izs[7];
        int bi = 0; float bw = w[0];
#pragma unroll
        for (int p = 1; p < 8; p++) if (w[p] > bw) { bw = w[p]; bi = p; }
        g_idx[b * Nn + n] = bi;
#pragma unroll
        for (int p = 0; p < 8; p++) {
            unsigned mk = __ballot_sync(FULLW, bi == p);
            if (lane == p) cc += __popc(mk);
        }
        const float* fb = feats + ((size_t)b * Nn + nb) * Dd;
#pragma unroll 4
        for (int r = 0; r < 32; r += 2) {
            float w1 = __shfl_sync(FULLW, bw, r);
            float w2 = __shfl_sync(FULLW, bw, r + 1);
            int   a1 = __shfl_sync(FULLW, bi, r);
            int   a2 = __shfl_sync(FULLW, bi, r + 1);
            const float4* p1 = (const float4*)(fb + (size_t)r * Dd) + lane * 2;
            const float4* p2 = (const float4*)(fb + (size_t)(r + 1) * Dd) + lane * 2;
            float4 x0 = p1[0], x1 = p1[1];
            float4 y0 = p2[0], y1 = p2[1];
#pragma unroll
            for (int p = 0; p < 8; p++) {
                float wa = (a1 == p) ? w1 : 0.f;
                float wb = (a2 == p) ? w2 : 0.f;
                acc[p][0] = fmaf(wa, x0.x, acc[p][0]); acc[p][1] = fmaf(wa, x0.y, acc[p][1]);
                acc[p][2] = fmaf(wa, x0.z, acc[p][2]); acc[p][3] = fmaf(wa, x0.w, acc[p][3]);
                acc[p][4] = fmaf(wa, x1.x, acc[p][4]); acc[p][5] = fmaf(wa, x1.y, acc[p][5]);
                acc[p][6] = fmaf(wa, x1.z, acc[p][6]); acc[p][7] = fmaf(wa, x1.w, acc[p][7]);
                acc[p][0] = fmaf(wb, y0.x, acc[p][0]); acc[p][1] = fmaf(wb, y0.y, acc[p][1]);
                acc[p][2] = fmaf(wb, y0.z, acc[p][2]); acc[p][3] = fmaf(wb, y0.w, acc[p][3]);
                acc[p][4] = fmaf(wb, y1.x, acc[p][4]); acc[p][5] = fmaf(wb, y1.y, acc[p][5]);
                acc[p][6] = fmaf(wb, y1.z, acc[p][6]); acc[p][7] = fmaf(wb, y1.w, acc[p][7]);
            }
        }
    }
    if (lane < 8) atomicAdd(&g_cnt[parw][b * 8 + lane], cc);

    // deterministic cross-warp reduction
    if (wid < 4) {
        float4* b4 = (float4*)buf[wid];
#pragma unroll
        for (int p = 0; p < 8; p++) {
            b4[p * 64 + lane * 2 + 0] = make_float4(acc[p][0], acc[p][1], acc[p][2], acc[p][3]);
            b4[p * 64 + lane * 2 + 1] = make_float4(acc[p][4], acc[p][5], acc[p][6], acc[p][7]);
        }
    }
    __syncthreads();
    if (wid >= 4) {
        float* bb = buf[wid - 4];
#pragma unroll
        for (int p = 0; p < 8; p++)
#pragma unroll
            for (int j = 0; j < 8; j++)
                bb[p * 256 + lane * 8 + j] += acc[p][j];
    }
    __syncthreads();
    float* op = g_ppart + ((size_t)(b * 8 + ch)) * 2048;
#pragma unroll
    for (int t = 0; t < 8; t++) {
        int i = t * 256 + tid;
        float v = ((buf[0][i] + buf[1][i]) + buf[2][i]) + buf[3][i];
        op[i] = v;
    }
}

// ---- reduce partials -> prototypes; fused normalize; reset state ----
__global__ void __launch_bounds__(256) k_reduce(float* __restrict__ outp, int parzero) {
    __shared__ float r8[8];
    int bp = blockIdx.x, b = bp >> 3, p = bp & 7;
    int tid = threadIdx.x;
    float v = 0.f;
#pragma unroll
    for (int c = 0; c < 8; c++)
        v += g_ppart[((size_t)(b * 8 + c)) * 2048 + p * 256 + tid];
    float ss = block_sum256(v * v, r8);
    float rn = 1.f / fmaxf(sqrtf(ss), EPSC);
    outp[(size_t)bp * Dd + tid] = v;
    g_pn[(size_t)bp * Dd + tid] = v * rn;
    if (tid == 0) { g_max[bp] = 0u; g_cnt[parzero][bp] = 0; }
}

// ---- final sim_map: pipelined like k_sim, rnorm computed inline ----
__global__ void __launch_bounds__(256) k_simmap(const float* __restrict__ forg,
                                                float* __restrict__ out) {
    int b = blockIdx.x >> 4, c = blockIdx.x & 15;
    int tid = threadIdx.x;
    __shared__ float4 pn_s[512];
    __shared__ float  fs[2][256 * 20];

    const float4* psrc = (const float4*)g_pn + (size_t)b * 512;
    for (int i = tid; i < 512; i += 256) pn_s[i] = psrc[i];

    const float4* fbase = (const float4*)forg + (size_t)c * 256 * 64;
    int rrow = tid >> 2, rj = tid & 3;
    const float4* gptr[4];
    int soff[4];
#pragma unroll
    for (int k = 0; k < 4; k++) {
        gptr[k] = fbase + (size_t)(k * 64 + rrow) * 64 + rj;
        soff[k] = (k * 64 + rrow) * 20 + rj * 4;
    }
    float4 r0[4];
#pragma unroll
    for (int k = 0; k < 4; k++) r0[k] = gptr[k][0];
#pragma unroll
    for (int k = 0; k < 4; k++) *(float4*)&fs[0][soff[k]] = r0[k];
    __syncthreads();

    float acc[8];
#pragma unroll
    for (int p = 0; p < 8; p++) acc[p] = 0.f;
    float sq = 0.f;

    for (int s = 0; s < 16; s++) {
        int buf = s & 1;
        if (s + 1 < 16) {
#pragma unroll
            for (int k = 0; k < 4; k++) r0[k] = gptr[k][(s + 1) * 4];
        }
#pragma unroll
        for (int j = 0; j < 4; j++) {
            float4 f = *(const float4*)&fs[buf][tid * 20 + j * 4];
            sq = fmaf(f.x, f.x, sq); sq = fmaf(f.y, f.y, sq);
            sq = fmaf(f.z, f.z, sq); sq = fmaf(f.w, f.w, sq);
#pragma unroll
            for (int p = 0; p < 8; p++) {
                float4 q = pn_s[p * 64 + s * 4 + j];
                acc[p] = fmaf(f.x, q.x, acc[p]); acc[p] = fmaf(f.y, q.y, acc[p]);
                acc[p] = fmaf(f.z, q.z, acc[p]); acc[p] = fmaf(f.w, q.w, acc[p]);
            }
        }
        if (s + 1 < 16) {
#pragma unroll
            for (int k = 0; k < 4; k++) *(float4*)&fs[buf ^ 1][soff[k]] = r0[k];
        }
        __syncthreads();
    }
    int m = c * 256 + tid;
    float rn = 1.f / fmaxf(sqrtf(sq), EPSC);
#pragma unroll
    for (int p = 0; p < 8; p++)
        out[((size_t)b * Pp + p) * Mm + m] = acc[p] * rn;
}

extern "C" void kernel_launch(void* const* d_in, const int* in_sizes, int n_in,
                              void* d_out, int out_size) {
    const float* protos = (const float*)d_in[0];
    const float* feats  = (const float*)d_in[1];
    const float* forg   = (const float*)d_in[2];
    float* out = (float*)d_out;

    k_norm0<<<BPc, 256>>>(protos);

    // iteration 0 (tau = 0.1 scalar)
    k_sim<true, false><<<Bb * 16, 256>>>(feats);
    k_stats<false><<<Bb * 4, 256>>>(0);
    k_update<<<BPc, 256>>>(feats, 0);
    k_reduce<<<BPc, 256>>>(out, 1);

    // iterations 1..4: sim pass doubles as previous iteration's density pass
    for (int t = 1; t < 5; t++) {
        k_sim<false, true><<<Bb * 16, 256>>>(feats);
        k_stats<true><<<Bb * 4, 256>>>((t - 1) & 1);
        k_update<<<BPc, 256>>>(feats, t & 1);
        k_reduce<<<BPc, 256>>>(out, (t + 1) & 1);
    }

    k_simmap<<<Bb * 16, 256>>>(forg, out + (size_t)BPc * Dd);
}